// round 9
// baseline (speedup 1.0000x reference)
#include <cuda_runtime.h>
#include <math.h>

#define BDIM 16
#define CO   64
#define RN   24            // Chebyshev nodes
#define CC   72            // padded channels: [0..63]=co, [64]=density, [65..71]=pad
#define RDIM 128
#define NBLK 256
#define NTHR 512

// ---------------- device globals ----------------
__device__ unsigned g_lo_u, g_hi_u;
__device__ int g_bar_cnt;
__device__ volatile int g_bar_gen;
__device__ __align__(16) float g_A[BDIM * RN * CC];      // atomically accumulated
__device__ __align__(16) float g_Btd[BDIM * RN];
__device__ __align__(16) float g_WB[BDIM * RN * RDIM];

__device__ __forceinline__ unsigned f2ord(float f) {
    unsigned u = __float_as_uint(f);
    return (u & 0x80000000u) ? ~u : (u | 0x80000000u);
}
__device__ __forceinline__ float ord2f(unsigned u) {
    return (u & 0x80000000u) ? __uint_as_float(u ^ 0x80000000u) : __uint_as_float(~u);
}

// software grid barrier: all NBLK blocks are co-resident by construction
__device__ __forceinline__ void grid_barrier() {
    __syncthreads();
    if (threadIdx.x == 0) {
        __threadfence();
        int gen = g_bar_gen;
        if (atomicAdd(&g_bar_cnt, 1) == NBLK - 1) {
            atomicExch(&g_bar_cnt, 0);
            __threadfence();
            g_bar_gen = gen + 1;
        } else {
            while (g_bar_gen == gen) { __nanosleep(64); }
        }
        __threadfence();
    }
    __syncthreads();
}

// ---------------- smem layout (floats) ----------------
#define P_S   0
#define P_W   RN                 // 24
#define P_K   (2 * RN)           // 48
#define P_MSC (P_K + RN * RN)    // 624  (0:a, 1:lo, 2:hi)
#define SCR   632                // scratch base (632*4 = 2528, 16B aligned)
// A: Lt[24][129]=3096 @SCR, co_s[128][18f4]=9216 @SCR+3096, invd[128] @SCR+12312
// B: As[1728] @SCR, Bt[1728] @SCR+1728, Ws[520] @SCR+3456
// C: Lat[24][132]=3168 @SCR, WBs[3072] @SCR+3168, dens[128] @SCR+6240,
//    Btd[24] @SCR+6368, W0s[128] @SCR+6392, bi[128] @SCR+6520
#define SM_FLOATS (SCR + 12440)  // 13072 floats = 52288 B

__global__ void __launch_bounds__(NTHR, 2)
k_all(const float* __restrict__ ci, const float* __restrict__ co,
      const float* __restrict__ ti, const float* __restrict__ ls,
      const float* __restrict__ W, const float* __restrict__ bias,
      float* __restrict__ out, int N, int M)
{
    extern __shared__ float sm[];
    const int tid = threadIdx.x, bid = blockIdx.x;

    // ================= phase 0: global min/max =================
    {
        const int nci = N * BDIM;
        const int total = nci + M * BDIM;
        float lo = 3.4e38f, hi = -3.4e38f;
        for (int i = bid * NTHR + tid; i < total; i += NBLK * NTHR) {
            float v = (i < nci) ? ci[i] : ti[i - nci];
            lo = fminf(lo, v);
            hi = fmaxf(hi, v);
        }
        #pragma unroll
        for (int o = 16; o; o >>= 1) {
            lo = fminf(lo, __shfl_xor_sync(0xFFFFFFFFu, lo, o));
            hi = fmaxf(hi, __shfl_xor_sync(0xFFFFFFFFu, hi, o));
        }
        if ((tid & 31) == 0) {
            atomicMin(&g_lo_u, f2ord(lo));
            atomicMax(&g_hi_u, f2ord(hi));
        }
    }
    grid_barrier();

    // ================= phase 1: per-block setup (s, w, K in smem) =================
    {
        if (tid == 0) {
            float l = ls[0];
            sm[P_MSC + 0] = -0.5f / (l * l);
            sm[P_MSC + 1] = ord2f(__ldcg(&g_lo_u));
            sm[P_MSC + 2] = ord2f(__ldcg(&g_hi_u));
        }
        __syncthreads();
        if (tid < RN) {
            float lo = sm[P_MSC + 1], hi = sm[P_MSC + 2];
            float c = 0.5f * (lo + hi);
            float h = 0.5f * (hi - lo) * 1.0002f + 1e-5f;
            double ang = (double)tid * M_PI / (double)(RN - 1);
            sm[P_S + tid] = c + h * (float)cos(ang);
            float wj = ((tid == 0) || (tid == RN - 1)) ? 0.5f : 1.0f;
            sm[P_W + tid] = (tid & 1) ? -wj : wj;
        }
        __syncthreads();
        float a = sm[P_MSC + 0];
        for (int i = tid; i < RN * RN; i += NTHR) {
            float d = sm[P_S + i / RN] - sm[P_S + i % RN];
            sm[P_K + i] = expf(a * d * d);
        }
        __syncthreads();
    }

    // ================= phase 2: stage A (atomic accumulate into g_A) =================
    {
        float* Lt   = sm + SCR;
        float* co_s = sm + SCR + 3096;
        float* invd = sm + SCR + 12312;
        const int b = bid >> 4, n0 = (bid & 15) * 128;

        if (tid < 128) {
            float x = ci[(n0 + tid) * BDIM + b];
            float den = 0.0f;
            #pragma unroll 8
            for (int j = 0; j < RN; ++j) {
                float d = x - sm[P_S + j];
                if (d == 0.0f) d = 1e-30f;
                float r = __fdividef(sm[P_W + j], d);
                den += r;
                Lt[j * 129 + tid] = r;
            }
            invd[tid] = __fdividef(1.0f, den);
        } else {
            for (int i = tid - 128; i < 128 * 18; i += NTHR - 128) {
                int nn = i / 18, c4 = i - nn * 18;
                float4 v;
                if (c4 < 16)
                    v = ((const float4*)(co + ((size_t)(n0 + nn) * BDIM + b) * CO))[c4];
                else if (c4 == 16)
                    v = make_float4(1.f, 0.f, 0.f, 0.f);
                else
                    v = make_float4(0.f, 0.f, 0.f, 0.f);
                ((float4*)co_s)[nn * 18 + c4] = v;
            }
        }
        __syncthreads();

        if (tid < 432) {   // 18 channel-groups x 24 q
            const int g = tid / 24, q = tid - g * 24;
            float4 acc = make_float4(0.f, 0.f, 0.f, 0.f);
            const float4* co4 = (const float4*)co_s;
            #pragma unroll 4
            for (int n = 0; n < 128; ++n) {
                float k = Lt[q * 129 + n] * invd[n];
                float4 x0 = co4[n * 18 + g];
                acc.x = fmaf(k, x0.x, acc.x); acc.y = fmaf(k, x0.y, acc.y);
                acc.z = fmaf(k, x0.z, acc.z); acc.w = fmaf(k, x0.w, acc.w);
            }
            float* ap = g_A + ((size_t)b * RN + q) * CC + g * 4;
            atomicAdd(ap + 0, acc.x); atomicAdd(ap + 1, acc.y);
            atomicAdd(ap + 2, acc.z); atomicAdd(ap + 3, acc.w);
        }
    }
    grid_barrier();

    // ================= phase 3: stage B  (Bt = K*A ; WB slice = Bt*W^T) =================
    {
        float* As = sm + SCR;
        float* Bt = sm + SCR + 1728;
        float* Ws = sm + SCR + 3456;
        const int b = bid >> 4, r0 = (bid & 15) * 8;

        for (int i = tid; i < RN * CC / 4; i += NTHR)
            ((float4*)As)[i] = __ldcg(((const float4*)(g_A + (size_t)b * RN * CC)) + i);
        for (int i = tid; i < 8 * 65; i += NTHR)
            Ws[i] = W[r0 * 65 + i];
        __syncthreads();

        for (int i = tid; i < RN * CC; i += NTHR) {
            int p = i / CC, c = i - p * CC;
            float acc = 0.0f;
            #pragma unroll 8
            for (int qq = 0; qq < RN; ++qq)
                acc = fmaf(sm[P_K + p * RN + qq], As[qq * CC + c], acc);
            Bt[i] = acc;
            if (c == 64 && r0 == 0) g_Btd[b * RN + p] = acc;
        }
        __syncthreads();

        for (int i = tid; i < RN * 8; i += NTHR) {
            int p = i >> 3, rr = i & 7;
            float acc = 0.0f;
            #pragma unroll 8
            for (int c = 0; c < 64; ++c)
                acc = fmaf(Ws[rr * 65 + (c + 1)], Bt[p * CC + c], acc);
            g_WB[((size_t)b * RN + p) * RDIM + r0 + rr] = acc;
        }
    }
    grid_barrier();

    // ================= phase 4: stage C (2 tiles per block, 4m x 8r per thread) =================
    float* Lat  = sm + SCR;
    float* WBs  = sm + SCR + 3168;
    float* dens = sm + SCR + 6240;
    float* Btd  = sm + SCR + 6368;
    float* W0s  = sm + SCR + 6392;
    float* bi_s = sm + SCR + 6520;

    for (int t = 0; t < 2; ++t) {
        const int tile = bid + NBLK * t;
        const int b = tile >> 5, m0 = (tile & 31) * 128;
        __syncthreads();   // protect smem reuse across phases/tiles

        for (int i = tid; i < RN * RDIM / 4; i += NTHR)
            ((float4*)WBs)[i] = __ldcg(((const float4*)(g_WB + (size_t)b * RN * RDIM)) + i);
        if (tid < RN) Btd[tid] = __ldcg(&g_Btd[b * RN + tid]);
        if (tid < 128) {
            W0s[tid]  = W[tid * 65];
            bi_s[tid] = bias[tid];
        }
        __syncthreads();

        if (tid < 128) {
            float x = ti[(m0 + tid) * BDIM + b];
            float den = 0.0f;
            #pragma unroll 8
            for (int j = 0; j < RN; ++j) {
                float d = x - sm[P_S + j];
                if (d == 0.0f) d = 1e-30f;
                float r = __fdividef(sm[P_W + j], d);
                den += r;
                Lat[j * 132 + tid] = r;
            }
            float inv = __fdividef(1.0f, den);
            float dm = 0.0f;
            #pragma unroll 8
            for (int j = 0; j < RN; ++j) {
                float v = Lat[j * 132 + tid] * inv;
                Lat[j * 132 + tid] = v;
                dm = fmaf(v, Btd[j], dm);
            }
            dens[tid] = dm;
        }
        __syncthreads();

        const int tx = tid & 31, ty = tid >> 5;   // tx: m (32x4), ty: r (16x8)
        const int mi = tx * 4, ri = ty * 8;
        float acc[4][8];
        #pragma unroll
        for (int k = 0; k < 4; ++k)
            #pragma unroll
            for (int j = 0; j < 8; ++j) acc[k][j] = 0.0f;

        const float4* Lat4 = (const float4*)Lat;
        const float4* WBs4 = (const float4*)WBs;
        #pragma unroll 4
        for (int p = 0; p < RN; ++p) {
            float4 a0 = Lat4[p * 33 + tx];
            float4 b0 = WBs4[p * 32 + ty * 2];
            float4 b1 = WBs4[p * 32 + ty * 2 + 1];
            float am[4] = {a0.x, a0.y, a0.z, a0.w};
            float br[8] = {b0.x, b0.y, b0.z, b0.w, b1.x, b1.y, b1.z, b1.w};
            #pragma unroll
            for (int k = 0; k < 4; ++k)
                #pragma unroll
                for (int j = 0; j < 8; ++j)
                    acc[k][j] = fmaf(am[k], br[j], acc[k][j]);
        }

        float w0[8], bi[8];
        #pragma unroll
        for (int j = 0; j < 8; ++j) { w0[j] = W0s[ri + j]; bi[j] = bi_s[ri + j]; }
        #pragma unroll
        for (int k = 0; k < 4; ++k) {
            float dm = dens[mi + k];
            float inv = __fdividef(1.0f, dm + 1e-8f);
            float o[8];
            #pragma unroll
            for (int j = 0; j < 8; ++j)
                o[j] = fmaf(acc[k][j], inv, fmaf(w0[j], dm, bi[j]));
            float* op = out + ((size_t)(m0 + mi + k) * BDIM + b) * RDIM + ri;
            ((float4*)op)[0] = make_float4(o[0], o[1], o[2], o[3]);
            ((float4*)op)[1] = make_float4(o[4], o[5], o[6], o[7]);
        }
    }
}

// ---------------- launch ----------------
extern "C" void kernel_launch(void* const* d_in, const int* in_sizes, int n_in,
                              void* d_out, int out_size)
{
    const float* ci   = (const float*)d_in[0];
    const float* co   = (const float*)d_in[1];
    const float* ti   = (const float*)d_in[2];
    const float* ls   = (const float*)d_in[3];
    const float* W    = (const float*)d_in[4];
    const float* bias = (const float*)d_in[5];
    float* out = (float*)d_out;

    const int N = in_sizes[0] / BDIM;   // 2048
    const int M = in_sizes[2] / BDIM;   // 4096

    cudaFuncSetAttribute(k_all, cudaFuncAttributeMaxDynamicSharedMemorySize,
                         SM_FLOATS * 4);

    void *p_lo, *p_hi, *p_A, *p_cnt, *p_gen;
    cudaGetSymbolAddress(&p_lo,  g_lo_u);
    cudaGetSymbolAddress(&p_hi,  g_hi_u);
    cudaGetSymbolAddress(&p_A,   g_A);
    cudaGetSymbolAddress(&p_cnt, (const void*)&g_bar_cnt);
    cudaGetSymbolAddress(&p_gen, (const void*)&g_bar_gen);
    cudaMemsetAsync(p_lo,  0xFF, 4);
    cudaMemsetAsync(p_hi,  0x00, 4);
    cudaMemsetAsync(p_cnt, 0x00, 4);
    cudaMemsetAsync(p_gen, 0x00, 4);
    cudaMemsetAsync(p_A,   0x00, BDIM * RN * CC * sizeof(float));

    k_all<<<NBLK, NTHR, SM_FLOATS * 4>>>(ci, co, ti, ls, W, bias, out, N, M);
}

// round 10
// speedup vs baseline: 1.2282x; 1.2282x over previous
#include <cuda_runtime.h>
#include <math.h>

#define BDIM 16
#define CO   64
#define RN   24            // Chebyshev nodes
#define CC   72            // padded channels: [0..63]=co, [64]=density, [65..71]=pad
#define RDIM 128
#define NBLK 256
#define NTHR 512
#define NCH  16            // n-chunks (N/128)

// ---------------- device globals ----------------
__device__ unsigned g_lo_u, g_hi_u;
__device__ int g_bar_cnt;
__device__ volatile int g_bar_gen;
__device__ __align__(16) float g_Apart[BDIM * NCH * RN * CC];   // per-chunk partials, 1.77MB
__device__ __align__(16) float g_Btd[BDIM * RN];
__device__ __align__(16) float g_WB[BDIM * RN * RDIM];

__device__ __forceinline__ unsigned f2ord(float f) {
    unsigned u = __float_as_uint(f);
    return (u & 0x80000000u) ? ~u : (u | 0x80000000u);
}
__device__ __forceinline__ float ord2f(unsigned u) {
    return (u & 0x80000000u) ? __uint_as_float(u ^ 0x80000000u) : __uint_as_float(~u);
}

__device__ __forceinline__ void grid_barrier() {
    __syncthreads();
    if (threadIdx.x == 0) {
        __threadfence();
        int gen = g_bar_gen;
        if (atomicAdd(&g_bar_cnt, 1) == NBLK - 1) {
            atomicExch(&g_bar_cnt, 0);
            __threadfence();
            g_bar_gen = gen + 1;
        } else {
            while (g_bar_gen == gen) { __nanosleep(64); }
        }
        __threadfence();
    }
    __syncthreads();
}

// ---------------- smem layout (floats) ----------------
#define P_S   0
#define P_W   RN
#define P_K   (2 * RN)           // 48
#define P_MSC (P_K + RN * RN)    // 624
#define SCR   632                // scratch base (2528 B, 16B aligned)
// A: Lt[24][129]=3096 @SCR, co_s[128][18f4]=9216 @SCR+3096, invd[128] @SCR+12312
// B: As[1728] @SCR, Bt[1728] @SCR+1728, Ws[520] @SCR+3456
// C: Lat[24][132]=3168 @SCR, WBs[3072] @SCR+3168, dens[128] @SCR+6240,
//    Btd[24] @SCR+6368, W0s[128] @SCR+6392, bi[128] @SCR+6520
#define SM_FLOATS (SCR + 12440)  // 52288 B

__global__ void __launch_bounds__(NTHR, 2)
k_all(const float* __restrict__ ci, const float* __restrict__ co,
      const float* __restrict__ ti, const float* __restrict__ ls,
      const float* __restrict__ W, const float* __restrict__ bias,
      float* __restrict__ out, int N, int M)
{
    extern __shared__ float sm[];
    const int tid = threadIdx.x, bid = blockIdx.x;

    // ================= phase 0: global min/max =================
    {
        const int nci = N * BDIM;
        const int total = nci + M * BDIM;
        float lo = 3.4e38f, hi = -3.4e38f;
        for (int i = bid * NTHR + tid; i < total; i += NBLK * NTHR) {
            float v = (i < nci) ? ci[i] : ti[i - nci];
            lo = fminf(lo, v);
            hi = fmaxf(hi, v);
        }
        #pragma unroll
        for (int o = 16; o; o >>= 1) {
            lo = fminf(lo, __shfl_xor_sync(0xFFFFFFFFu, lo, o));
            hi = fmaxf(hi, __shfl_xor_sync(0xFFFFFFFFu, hi, o));
        }
        if ((tid & 31) == 0) {
            atomicMin(&g_lo_u, f2ord(lo));
            atomicMax(&g_hi_u, f2ord(hi));
        }
    }
    grid_barrier();

    // ================= phase 1: per-block setup =================
    {
        if (tid == 0) {
            float l = ls[0];
            sm[P_MSC + 0] = -0.5f / (l * l);
            sm[P_MSC + 1] = ord2f(__ldcg(&g_lo_u));
            sm[P_MSC + 2] = ord2f(__ldcg(&g_hi_u));
        }
        __syncthreads();
        if (tid < RN) {
            float lo = sm[P_MSC + 1], hi = sm[P_MSC + 2];
            float c = 0.5f * (lo + hi);
            float h = 0.5f * (hi - lo) * 1.0002f + 1e-5f;
            double ang = (double)tid * M_PI / (double)(RN - 1);
            sm[P_S + tid] = c + h * (float)cos(ang);
            float wj = ((tid == 0) || (tid == RN - 1)) ? 0.5f : 1.0f;
            sm[P_W + tid] = (tid & 1) ? -wj : wj;
        }
        __syncthreads();
        float a = sm[P_MSC + 0];
        for (int i = tid; i < RN * RN; i += NTHR) {
            float d = sm[P_S + i / RN] - sm[P_S + i % RN];
            sm[P_K + i] = expf(a * d * d);
        }
        __syncthreads();
    }

    // ================= phase 2: stage A -> per-chunk partials (no atomics) =================
    {
        float* Lt   = sm + SCR;
        float* co_s = sm + SCR + 3096;
        float* invd = sm + SCR + 12312;
        const int b = bid >> 4, chunk = bid & 15, n0 = chunk * 128;

        if (tid < 128) {
            float x = ci[(n0 + tid) * BDIM + b];
            float den = 0.0f;
            #pragma unroll 8
            for (int j = 0; j < RN; ++j) {
                float d = x - sm[P_S + j];
                if (d == 0.0f) d = 1e-30f;
                float r = __fdividef(sm[P_W + j], d);
                den += r;
                Lt[j * 129 + tid] = r;
            }
            invd[tid] = __fdividef(1.0f, den);
        } else {
            for (int i = tid - 128; i < 128 * 18; i += NTHR - 128) {
                int nn = i / 18, c4 = i - nn * 18;
                float4 v;
                if (c4 < 16)
                    v = ((const float4*)(co + ((size_t)(n0 + nn) * BDIM + b) * CO))[c4];
                else if (c4 == 16)
                    v = make_float4(1.f, 0.f, 0.f, 0.f);
                else
                    v = make_float4(0.f, 0.f, 0.f, 0.f);
                ((float4*)co_s)[nn * 18 + c4] = v;
            }
        }
        __syncthreads();

        if (tid < 432) {   // 18 channel-groups x 24 q
            const int g = tid / 24, q = tid - g * 24;
            float4 acc = make_float4(0.f, 0.f, 0.f, 0.f);
            const float4* co4 = (const float4*)co_s;
            #pragma unroll 4
            for (int n = 0; n < 128; ++n) {
                float k = Lt[q * 129 + n] * invd[n];
                float4 x0 = co4[n * 18 + g];
                acc.x = fmaf(k, x0.x, acc.x); acc.y = fmaf(k, x0.y, acc.y);
                acc.z = fmaf(k, x0.z, acc.z); acc.w = fmaf(k, x0.w, acc.w);
            }
            float4* ap = (float4*)(g_Apart + (((size_t)b * NCH + chunk) * RN + q) * CC) + g;
            *ap = acc;
        }
    }
    grid_barrier();

    // ================= phase 3: stage B  (chunk-sum; Bt = K*A ; WB slice) =================
    {
        float* As = sm + SCR;
        float* Bt = sm + SCR + 1728;
        float* Ws = sm + SCR + 3456;
        const int b = bid >> 4, r0 = (bid & 15) * 8;

        for (int i = tid; i < RN * CC / 4; i += NTHR) {
            const float4* base = (const float4*)(g_Apart + (size_t)b * NCH * RN * CC) + i;
            float4 s = make_float4(0.f, 0.f, 0.f, 0.f);
            #pragma unroll
            for (int ch = 0; ch < NCH; ++ch) {
                float4 v = __ldcg(base + ch * (RN * CC / 4));
                s.x += v.x; s.y += v.y; s.z += v.z; s.w += v.w;
            }
            ((float4*)As)[i] = s;
        }
        for (int i = tid; i < 8 * 65; i += NTHR)
            Ws[i] = W[r0 * 65 + i];
        __syncthreads();

        for (int i = tid; i < RN * CC; i += NTHR) {
            int p = i / CC, c = i - p * CC;
            float acc = 0.0f;
            #pragma unroll 8
            for (int qq = 0; qq < RN; ++qq)
                acc = fmaf(sm[P_K + p * RN + qq], As[qq * CC + c], acc);
            Bt[i] = acc;
            if (c == 64 && r0 == 0) g_Btd[b * RN + p] = acc;
        }
        __syncthreads();

        for (int i = tid; i < RN * 8; i += NTHR) {
            int p = i >> 3, rr = i & 7;
            float acc = 0.0f;
            #pragma unroll 8
            for (int c = 0; c < 64; ++c)
                acc = fmaf(Ws[rr * 65 + (c + 1)], Bt[p * CC + c], acc);
            g_WB[((size_t)b * RN + p) * RDIM + r0 + rr] = acc;
        }
    }
    grid_barrier();

    // ================= phase 4: stage C — warp = 8 m-rows, lane = r-float4 =================
    float* Lat  = sm + SCR;
    float* WBs  = sm + SCR + 3168;
    float* dens = sm + SCR + 6240;
    float* Btd  = sm + SCR + 6368;
    float* W0s  = sm + SCR + 6392;
    float* bi_s = sm + SCR + 6520;

    const int w = tid >> 5, l = tid & 31;

    for (int t = 0; t < 2; ++t) {
        const int tile = bid + NBLK * t;
        const int b = tile >> 5, m0 = (tile & 31) * 128;
        __syncthreads();

        for (int i = tid; i < RN * RDIM / 4; i += NTHR)
            ((float4*)WBs)[i] = __ldcg(((const float4*)(g_WB + (size_t)b * RN * RDIM)) + i);
        if (tid < RN) Btd[tid] = __ldcg(&g_Btd[b * RN + tid]);
        if (tid < 128) {
            W0s[tid]  = W[tid * 65];
            bi_s[tid] = bias[tid];
        }
        __syncthreads();

        if (tid < 128) {
            float x = ti[(m0 + tid) * BDIM + b];
            float den = 0.0f;
            #pragma unroll 8
            for (int j = 0; j < RN; ++j) {
                float d = x - sm[P_S + j];
                if (d == 0.0f) d = 1e-30f;
                float r = __fdividef(sm[P_W + j], d);
                den += r;
                Lat[j * 132 + tid] = r;
            }
            float inv = __fdividef(1.0f, den);
            float dm = 0.0f;
            #pragma unroll 8
            for (int j = 0; j < RN; ++j) {
                float v = Lat[j * 132 + tid] * inv;
                Lat[j * 132 + tid] = v;
                dm = fmaf(v, Btd[j], dm);
            }
            dens[tid] = dm;
        }
        __syncthreads();

        // 8 m-rows per warp (mw0..mw0+7), lane l covers r = 4l..4l+3
        const int mw0 = w * 8;
        unsigned long long acc01[8], acc23[8];
        #pragma unroll
        for (int k = 0; k < 8; ++k) { acc01[k] = 0ull; acc23[k] = 0ull; }

        const float4* WBs4 = (const float4*)WBs;
        #pragma unroll 4
        for (int p = 0; p < RN; ++p) {
            float4 wv = WBs4[p * 32 + l];                 // conflict-free 512B/warp
            unsigned long long wv01, wv23;
            asm("mov.b64 %0, {%1,%2};" : "=l"(wv01) : "f"(wv.x), "f"(wv.y));
            asm("mov.b64 %0, {%1,%2};" : "=l"(wv23) : "f"(wv.z), "f"(wv.w));
            const float4* lmp = (const float4*)(Lat + p * 132 + mw0);   // broadcast
            float4 lma = lmp[0], lmb = lmp[1];
            float lm[8] = {lma.x, lma.y, lma.z, lma.w, lmb.x, lmb.y, lmb.z, lmb.w};
            #pragma unroll
            for (int k = 0; k < 8; ++k) {
                unsigned long long lm2;
                asm("mov.b64 %0, {%1,%1};" : "=l"(lm2) : "f"(lm[k]));
                asm("fma.rn.f32x2 %0, %1, %2, %0;" : "+l"(acc01[k]) : "l"(lm2), "l"(wv01));
                asm("fma.rn.f32x2 %0, %1, %2, %0;" : "+l"(acc23[k]) : "l"(lm2), "l"(wv23));
            }
        }

        float4 w04 = ((const float4*)W0s)[l];
        float4 bi4 = ((const float4*)bi_s)[l];
        #pragma unroll
        for (int k = 0; k < 8; ++k) {
            float dm = dens[mw0 + k];
            float inv = __fdividef(1.0f, dm + 1e-8f);
            float a0, a1, a2, a3;
            asm("mov.b64 {%0,%1}, %2;" : "=f"(a0), "=f"(a1) : "l"(acc01[k]));
            asm("mov.b64 {%0,%1}, %2;" : "=f"(a2), "=f"(a3) : "l"(acc23[k]));
            float4 o;
            o.x = fmaf(a0, inv, fmaf(w04.x, dm, bi4.x));
            o.y = fmaf(a1, inv, fmaf(w04.y, dm, bi4.y));
            o.z = fmaf(a2, inv, fmaf(w04.z, dm, bi4.z));
            o.w = fmaf(a3, inv, fmaf(w04.w, dm, bi4.w));
            // lanes write 512B contiguous per m-row
            ((float4*)(out + ((size_t)(m0 + mw0 + k) * BDIM + b) * RDIM))[l] = o;
        }
    }
}

// ---------------- launch ----------------
extern "C" void kernel_launch(void* const* d_in, const int* in_sizes, int n_in,
                              void* d_out, int out_size)
{
    const float* ci   = (const float*)d_in[0];
    const float* co   = (const float*)d_in[1];
    const float* ti   = (const float*)d_in[2];
    const float* ls   = (const float*)d_in[3];
    const float* W    = (const float*)d_in[4];
    const float* bias = (const float*)d_in[5];
    float* out = (float*)d_out;

    const int N = in_sizes[0] / BDIM;   // 2048
    const int M = in_sizes[2] / BDIM;   // 4096

    cudaFuncSetAttribute(k_all, cudaFuncAttributeMaxDynamicSharedMemorySize,
                         SM_FLOATS * 4);

    void *p_lo, *p_hi, *p_cnt, *p_gen;
    cudaGetSymbolAddress(&p_lo,  g_lo_u);
    cudaGetSymbolAddress(&p_hi,  g_hi_u);
    cudaGetSymbolAddress(&p_cnt, (const void*)&g_bar_cnt);
    cudaGetSymbolAddress(&p_gen, (const void*)&g_bar_gen);
    cudaMemsetAsync(p_lo,  0xFF, 4);
    cudaMemsetAsync(p_hi,  0x00, 4);
    cudaMemsetAsync(p_cnt, 0x00, 4);
    cudaMemsetAsync(p_gen, 0x00, 4);

    k_all<<<NBLK, NTHR, SM_FLOATS * 4>>>(ci, co, ti, ls, W, bias, out, N, M);
}

// round 11
// speedup vs baseline: 1.3121x; 1.0683x over previous
#include <cuda_runtime.h>
#include <math.h>

#define BDIM 16
#define CO   64
#define RN   24            // Chebyshev nodes
#define CC   72            // padded channels: [0..63]=co, [64]=density, [65..71]=pad
#define RDIM 128
#define NBLK 256
#define NTHR 512
#define NCH  16            // n-chunks (N/128)

// ---------------- device globals ----------------
__device__ unsigned g_lo_u, g_hi_u;
__device__ int g_bar_cnt;
__device__ volatile int g_bar_gen;
__device__ __align__(16) float g_Apart[BDIM * NCH * RN * CC];   // per-chunk partials
__device__ __align__(16) float g_Btd[BDIM * RN];
__device__ __align__(16) float g_WB[BDIM * RN * RDIM];

__device__ __forceinline__ unsigned f2ord(float f) {
    unsigned u = __float_as_uint(f);
    return (u & 0x80000000u) ? ~u : (u | 0x80000000u);
}
__device__ __forceinline__ float ord2f(unsigned u) {
    return (u & 0x80000000u) ? __uint_as_float(u ^ 0x80000000u) : __uint_as_float(~u);
}

__device__ __forceinline__ void grid_barrier() {
    __syncthreads();
    if (threadIdx.x == 0) {
        __threadfence();
        int gen = g_bar_gen;
        if (atomicAdd(&g_bar_cnt, 1) == NBLK - 1) {
            atomicExch(&g_bar_cnt, 0);
            __threadfence();
            g_bar_gen = gen + 1;
        } else {
            while (g_bar_gen == gen) { __nanosleep(64); }
        }
        __threadfence();
    }
    __syncthreads();
}

// ---------------- smem layout (floats) ----------------
#define P_S   0
#define P_W   RN
#define P_K   (2 * RN)           // 48
#define P_MSC (P_K + RN * RN)    // 624
#define SCR   632                // scratch base (2528 B, 16B aligned)
// phase 2: Ltn[128][28]=3584 @SCR, co_s[128][17 fl4]=8704 @SCR+3584 (reduce overlay reuses co_s)
// phase 3: As[1728] @SCR, Bt[1728] @SCR+1728, Ws[520] @SCR+3456
// phase 4: Lat[24][132]=3168 @SCR, WBs[3072] @SCR+3168, dens[128] @SCR+6240,
//          Btd[24] @SCR+6368, W0s[128] @SCR+6392, bi[128] @SCR+6520
#define SM_FLOATS (SCR + 12440)  // 52288 B

__global__ void __launch_bounds__(NTHR, 2)
k_all(const float* __restrict__ ci, const float* __restrict__ co,
      const float* __restrict__ ti, const float* __restrict__ ls,
      const float* __restrict__ W, const float* __restrict__ bias,
      float* __restrict__ out, int N, int M)
{
    extern __shared__ float sm[];
    const int tid = threadIdx.x, bid = blockIdx.x;
    const int b2 = bid >> 4, chunk = bid & 15, n0 = chunk * 128;

    // ================= phase 0: global min/max + co_s prefetch =================
    {
        const int nci = N * BDIM;
        const int total = nci + M * BDIM;
        float lo = 3.4e38f, hi = -3.4e38f;
        for (int i = bid * NTHR + tid; i < total; i += NBLK * NTHR) {
            float v = (i < nci) ? ci[i] : ti[i - nci];
            lo = fminf(lo, v);
            hi = fmaxf(hi, v);
        }
        #pragma unroll
        for (int o = 16; o; o >>= 1) {
            lo = fminf(lo, __shfl_xor_sync(0xFFFFFFFFu, lo, o));
            hi = fmaxf(hi, __shfl_xor_sync(0xFFFFFFFFu, hi, o));
        }
        if ((tid & 31) == 0) {
            atomicMin(&g_lo_u, f2ord(lo));
            atomicMax(&g_hi_u, f2ord(hi));
        }
        // prefetch co tile for phase 2 (hides gmem latency behind barrier)
        float4* co_s4 = (float4*)(sm + SCR + 3584);
        for (int i = tid; i < 128 * 17; i += NTHR) {
            int nn = i / 17, c4 = i - nn * 17;
            float4 v = (c4 < 16)
                ? ((const float4*)(co + ((size_t)(n0 + nn) * BDIM + b2) * CO))[c4]
                : make_float4(1.f, 0.f, 0.f, 0.f);
            co_s4[i] = v;
        }
    }
    grid_barrier();

    // ================= phase 1: per-block setup =================
    {
        if (tid == 0) {
            float l = ls[0];
            sm[P_MSC + 0] = -0.5f / (l * l);
            sm[P_MSC + 1] = ord2f(__ldcg(&g_lo_u));
            sm[P_MSC + 2] = ord2f(__ldcg(&g_hi_u));
        }
        __syncthreads();
        if (tid < RN) {
            float lo = sm[P_MSC + 1], hi = sm[P_MSC + 2];
            float c = 0.5f * (lo + hi);
            float h = 0.5f * (hi - lo) * 1.0002f + 1e-5f;
            double ang = (double)tid * M_PI / (double)(RN - 1);
            sm[P_S + tid] = c + h * (float)cos(ang);
            float wj = ((tid == 0) || (tid == RN - 1)) ? 0.5f : 1.0f;
            sm[P_W + tid] = (tid & 1) ? -wj : wj;
        }
        __syncthreads();
        float a = sm[P_MSC + 0];
        for (int i = tid; i < RN * RN; i += NTHR) {
            float d = sm[P_S + i / RN] - sm[P_S + i % RN];
            sm[P_K + i] = expf(a * d * d);
        }
        __syncthreads();
    }

    // ================= phase 2: stage A — 4q x 4c register tiles =================
    {
        float* Ltn  = sm + SCR;             // [128][28], pre-normalized
        float* co_s = sm + SCR + 3584;      // [128][17 fl4]

        if (tid < 128) {
            float x = ci[(n0 + tid) * BDIM + b2];
            float den = 0.0f;
            float* lr = Ltn + tid * 28;
            #pragma unroll 8
            for (int j = 0; j < RN; ++j) {
                float d = x - sm[P_S + j];
                if (d == 0.0f) d = 1e-30f;
                float r = __fdividef(sm[P_W + j], d);
                den += r;
                lr[j] = r;
            }
            float inv = __fdividef(1.0f, den);
            #pragma unroll 8
            for (int j = 0; j < RN; ++j) lr[j] *= inv;
        }
        __syncthreads();

        const bool act = (tid < 408);
        int slice = 0, qg = 0, cg = 0;
        float acc[4][4];
        #pragma unroll
        for (int qi = 0; qi < 4; ++qi)
            #pragma unroll
            for (int ci4 = 0; ci4 < 4; ++ci4) acc[qi][ci4] = 0.0f;

        if (act) {
            slice = tid / 102;
            int rem = tid - slice * 102;
            qg = rem / 17; cg = rem - qg * 17;
            const float4* Lt4 = (const float4*)Ltn;
            const float4* co4 = (const float4*)co_s;
            const int nb = slice * 32;
            #pragma unroll 4
            for (int i = 0; i < 32; ++i) {
                int n = nb + i;
                float4 lt = Lt4[n * 7 + qg];
                float4 cv = co4[n * 17 + cg];
                float lq[4] = {lt.x, lt.y, lt.z, lt.w};
                #pragma unroll
                for (int qi = 0; qi < 4; ++qi) {
                    acc[qi][0] = fmaf(lq[qi], cv.x, acc[qi][0]);
                    acc[qi][1] = fmaf(lq[qi], cv.y, acc[qi][1]);
                    acc[qi][2] = fmaf(lq[qi], cv.z, acc[qi][2]);
                    acc[qi][3] = fmaf(lq[qi], cv.w, acc[qi][3]);
                }
            }
        }
        __syncthreads();   // everyone done reading co_s/Ltn

        float4* red = (float4*)(sm + SCR + 3584);   // overlay on co_s: 3*102*4 fl4
        if (act && slice > 0) {
            int rem = tid - slice * 102;
            #pragma unroll
            for (int qi = 0; qi < 4; ++qi)
                red[((slice - 1) * 102 + rem) * 4 + qi] =
                    make_float4(acc[qi][0], acc[qi][1], acc[qi][2], acc[qi][3]);
        }
        __syncthreads();

        if (tid < 102) {
            #pragma unroll
            for (int s = 0; s < 3; ++s)
                #pragma unroll
                for (int qi = 0; qi < 4; ++qi) {
                    float4 v = red[(s * 102 + tid) * 4 + qi];
                    acc[qi][0] += v.x; acc[qi][1] += v.y;
                    acc[qi][2] += v.z; acc[qi][3] += v.w;
                }
            const int q0 = qg * 4, c0 = cg * 4;
            #pragma unroll
            for (int qi = 0; qi < 4; ++qi) {
                float4* ap = (float4*)(g_Apart +
                    (((size_t)b2 * NCH + chunk) * RN + q0 + qi) * CC + c0);
                *ap = make_float4(acc[qi][0], acc[qi][1], acc[qi][2], acc[qi][3]);
            }
        }
    }
    grid_barrier();

    // ================= phase 3: stage B (chunk-sum; Bt = K*A ; WB slice) =================
    {
        float* As = sm + SCR;
        float* Bt = sm + SCR + 1728;
        float* Ws = sm + SCR + 3456;
        const int b = bid >> 4, r0 = (bid & 15) * 8;

        for (int i = tid; i < RN * CC / 4; i += NTHR) {
            const float4* base = (const float4*)(g_Apart + (size_t)b * NCH * RN * CC) + i;
            float4 s = make_float4(0.f, 0.f, 0.f, 0.f);
            #pragma unroll
            for (int ch = 0; ch < NCH; ++ch) {
                float4 v = __ldcg(base + ch * (RN * CC / 4));
                s.x += v.x; s.y += v.y; s.z += v.z; s.w += v.w;
            }
            ((float4*)As)[i] = s;
        }
        for (int i = tid; i < 8 * 65; i += NTHR)
            Ws[i] = W[r0 * 65 + i];
        __syncthreads();

        for (int i = tid; i < RN * CC; i += NTHR) {
            int p = i / CC, c = i - p * CC;
            float acc = 0.0f;
            #pragma unroll 8
            for (int qq = 0; qq < RN; ++qq)
                acc = fmaf(sm[P_K + p * RN + qq], As[qq * CC + c], acc);
            Bt[i] = acc;
            if (c == 64 && r0 == 0) g_Btd[b * RN + p] = acc;
        }
        __syncthreads();

        for (int i = tid; i < RN * 8; i += NTHR) {
            int p = i >> 3, rr = i & 7;
            float acc = 0.0f;
            #pragma unroll 8
            for (int c = 0; c < 64; ++c)
                acc = fmaf(Ws[rr * 65 + (c + 1)], Bt[p * CC + c], acc);
            g_WB[((size_t)b * RN + p) * RDIM + r0 + rr] = acc;
        }
    }
    grid_barrier();

    // ================= phase 4: stage C — warp = 8 m-rows, lane = r-float4 =================
    float* Lat  = sm + SCR;
    float* WBs  = sm + SCR + 3168;
    float* dens = sm + SCR + 6240;
    float* Btd  = sm + SCR + 6368;
    float* W0s  = sm + SCR + 6392;
    float* bi_s = sm + SCR + 6520;

    const int w = tid >> 5, l = tid & 31;

    for (int t = 0; t < 2; ++t) {
        const int tile = bid + NBLK * t;
        const int b = tile >> 5, m0 = (tile & 31) * 128;
        __syncthreads();

        for (int i = tid; i < RN * RDIM / 4; i += NTHR)
            ((float4*)WBs)[i] = __ldcg(((const float4*)(g_WB + (size_t)b * RN * RDIM)) + i);
        if (tid < RN) Btd[tid] = __ldcg(&g_Btd[b * RN + tid]);
        if (tid < 128) {
            W0s[tid]  = W[tid * 65];
            bi_s[tid] = bias[tid];
        }
        __syncthreads();

        if (tid < 128) {
            float x = ti[(m0 + tid) * BDIM + b];
            float den = 0.0f;
            #pragma unroll 8
            for (int j = 0; j < RN; ++j) {
                float d = x - sm[P_S + j];
                if (d == 0.0f) d = 1e-30f;
                float r = __fdividef(sm[P_W + j], d);
                den += r;
                Lat[j * 132 + tid] = r;
            }
            float inv = __fdividef(1.0f, den);
            float dm = 0.0f;
            #pragma unroll 8
            for (int j = 0; j < RN; ++j) {
                float v = Lat[j * 132 + tid] * inv;
                Lat[j * 132 + tid] = v;
                dm = fmaf(v, Btd[j], dm);
            }
            dens[tid] = dm;
        }
        __syncthreads();

        const int mw0 = w * 8;
        unsigned long long acc01[8], acc23[8];
        #pragma unroll
        for (int k = 0; k < 8; ++k) { acc01[k] = 0ull; acc23[k] = 0ull; }

        const float4* WBs4 = (const float4*)WBs;
        #pragma unroll 4
        for (int p = 0; p < RN; ++p) {
            float4 wv = WBs4[p * 32 + l];                 // conflict-free 512B/warp
            unsigned long long wv01, wv23;
            asm("mov.b64 %0, {%1,%2};" : "=l"(wv01) : "f"(wv.x), "f"(wv.y));
            asm("mov.b64 %0, {%1,%2};" : "=l"(wv23) : "f"(wv.z), "f"(wv.w));
            const float4* lmp = (const float4*)(Lat + p * 132 + mw0);   // broadcast
            float4 lma = lmp[0], lmb = lmp[1];
            float lm[8] = {lma.x, lma.y, lma.z, lma.w, lmb.x, lmb.y, lmb.z, lmb.w};
            #pragma unroll
            for (int k = 0; k < 8; ++k) {
                unsigned long long lm2;
                asm("mov.b64 %0, {%1,%1};" : "=l"(lm2) : "f"(lm[k]));
                asm("fma.rn.f32x2 %0, %1, %2, %0;" : "+l"(acc01[k]) : "l"(lm2), "l"(wv01));
                asm("fma.rn.f32x2 %0, %1, %2, %0;" : "+l"(acc23[k]) : "l"(lm2), "l"(wv23));
            }
        }

        float4 w04 = ((const float4*)W0s)[l];
        float4 bi4 = ((const float4*)bi_s)[l];
        #pragma unroll
        for (int k = 0; k < 8; ++k) {
            float dm = dens[mw0 + k];
            float inv = __fdividef(1.0f, dm + 1e-8f);
            float a0, a1, a2, a3;
            asm("mov.b64 {%0,%1}, %2;" : "=f"(a0), "=f"(a1) : "l"(acc01[k]));
            asm("mov.b64 {%0,%1}, %2;" : "=f"(a2), "=f"(a3) : "l"(acc23[k]));
            float4 o;
            o.x = fmaf(a0, inv, fmaf(w04.x, dm, bi4.x));
            o.y = fmaf(a1, inv, fmaf(w04.y, dm, bi4.y));
            o.z = fmaf(a2, inv, fmaf(w04.z, dm, bi4.z));
            o.w = fmaf(a3, inv, fmaf(w04.w, dm, bi4.w));
            ((float4*)(out + ((size_t)(m0 + mw0 + k) * BDIM + b) * RDIM))[l] = o;
        }
    }
}

// ---------------- launch ----------------
extern "C" void kernel_launch(void* const* d_in, const int* in_sizes, int n_in,
                              void* d_out, int out_size)
{
    const float* ci   = (const float*)d_in[0];
    const float* co   = (const float*)d_in[1];
    const float* ti   = (const float*)d_in[2];
    const float* ls   = (const float*)d_in[3];
    const float* W    = (const float*)d_in[4];
    const float* bias = (const float*)d_in[5];
    float* out = (float*)d_out;

    const int N = in_sizes[0] / BDIM;   // 2048
    const int M = in_sizes[2] / BDIM;   // 4096

    cudaFuncSetAttribute(k_all, cudaFuncAttributeMaxDynamicSharedMemorySize,
                         SM_FLOATS * 4);

    void *p_lo, *p_hi, *p_cnt, *p_gen;
    cudaGetSymbolAddress(&p_lo,  g_lo_u);
    cudaGetSymbolAddress(&p_hi,  g_hi_u);
    cudaGetSymbolAddress(&p_cnt, (const void*)&g_bar_cnt);
    cudaGetSymbolAddress(&p_gen, (const void*)&g_bar_gen);
    cudaMemsetAsync(p_lo,  0xFF, 4);
    cudaMemsetAsync(p_hi,  0x00, 4);
    cudaMemsetAsync(p_cnt, 0x00, 4);
    cudaMemsetAsync(p_gen, 0x00, 4);

    k_all<<<NBLK, NTHR, SM_FLOATS * 4>>>(ci, co, ti, ls, W, bias, out, N, M);
}